// round 4
// baseline (speedup 1.0000x reference)
#include <cuda_runtime.h>

#define Bn 4
#define Ln 200
#define Hn 256
#define NHn 4
#define HSn 64

__device__ float4 g_Q4 [Bn * Ln * (Hn / 4)];
__device__ float4 g_Kc4[Bn * Ln * (Hn / 4)];
__device__ float4 g_Vc4[Bn * Ln * (Hn / 4)];

#define PROJ_ROWS 2
#define KC 8
#define WPITCH 260   // 260 % 32 == 4 -> staging scatter is a bank permutation

// ---------------------------------------------------------------------------
// Projection: Q = x@Qw^T+Qb ; Kc = k@Kw^T+Kb+pK ; Vc = k@Vw^T+Vb+pV
// ---------------------------------------------------------------------------
__global__ __launch_bounds__(256)
void proj_kernel(const float4* __restrict__ queries,
                 const float4* __restrict__ keys,
                 const float* __restrict__ apK,
                 const float* __restrict__ apV,
                 const float4* __restrict__ Qw4, const float* __restrict__ Qb,
                 const float4* __restrict__ Kw4, const float* __restrict__ Kb,
                 const float4* __restrict__ Vw4, const float* __restrict__ Vb)
{
    __shared__ alignas(16) float xq[PROJ_ROWS][Hn];
    __shared__ alignas(16) float xk[PROJ_ROWS][Hn];
    __shared__ float wq[KC][WPITCH], wk[KC][WPITCH], wv[KC][WPITCH];

    const int r0 = blockIdx.x * PROJ_ROWS;
    const int t  = threadIdx.x;

    // stage x rows (coalesced float4): 2 rows x 64 float4 = 128 units
    if (t < 128) {
        const int rr = t >> 6;            // FIX (was t >> 7): row within pair
        const int c4 = t & 63;            // float4 index within row
        float4 vq = queries[(r0 + rr) * 64 + c4];
        float4 vk = keys   [(r0 + rr) * 64 + c4];
        reinterpret_cast<float4*>(&xq[rr][0])[c4] = vq;
        reinterpret_cast<float4*>(&xk[rr][0])[c4] = vk;
    }

    float accq[PROJ_ROWS], acck[PROJ_ROWS], accv[PROJ_ROWS];
    #pragma unroll
    for (int r = 0; r < PROJ_ROWS; ++r) { accq[r] = 0.f; acck[r] = 0.f; accv[r] = 0.f; }

    for (int i0 = 0; i0 < Hn; i0 += KC) {
        __syncthreads();
        // stage W chunk: 256 rows x 2 float4 per array; 2 per thread
        #pragma unroll
        for (int u = 0; u < 2; ++u) {
            const int e = t + u * 256;    // 0..511
            const int j = e >> 1;         // weight row (output col)
            const int q = e & 1;          // which float4 within the 8-chunk
            const int gidx = j * (Hn / 4) + (i0 >> 2) + q;
            const float4 fq = Qw4[gidx];
            const float4 fk = Kw4[gidx];
            const float4 fv = Vw4[gidx];
            const int ii = q * 4;
            wq[ii+0][j] = fq.x; wq[ii+1][j] = fq.y; wq[ii+2][j] = fq.z; wq[ii+3][j] = fq.w;
            wk[ii+0][j] = fk.x; wk[ii+1][j] = fk.y; wk[ii+2][j] = fk.z; wk[ii+3][j] = fk.w;
            wv[ii+0][j] = fv.x; wv[ii+1][j] = fv.y; wv[ii+2][j] = fv.z; wv[ii+3][j] = fv.w;
        }
        __syncthreads();

        #pragma unroll
        for (int q = 0; q < 2; ++q) {
            float4 xqv[PROJ_ROWS], xkv[PROJ_ROWS];
            #pragma unroll
            for (int r = 0; r < PROJ_ROWS; ++r) {
                xqv[r] = reinterpret_cast<const float4*>(&xq[r][0])[(i0 >> 2) + q];
                xkv[r] = reinterpret_cast<const float4*>(&xk[r][0])[(i0 >> 2) + q];
            }
            #pragma unroll
            for (int k = 0; k < 4; ++k) {
                const int ii = q * 4 + k;
                const float aq = wq[ii][t], ak = wk[ii][t], av = wv[ii][t];
                #pragma unroll
                for (int r = 0; r < PROJ_ROWS; ++r) {
                    const float xqs = (k == 0) ? xqv[r].x : (k == 1) ? xqv[r].y : (k == 2) ? xqv[r].z : xqv[r].w;
                    const float xks = (k == 0) ? xkv[r].x : (k == 1) ? xkv[r].y : (k == 2) ? xkv[r].z : xkv[r].w;
                    accq[r] += xqs * aq;
                    acck[r] += xks * ak;
                    accv[r] += xks * av;
                }
            }
        }
    }

    const float bq = Qb[t], bk = Kb[t], bv = Vb[t];
    float* gQ  = (float*)g_Q4;
    float* gKc = (float*)g_Kc4;
    float* gVc = (float*)g_Vc4;
    #pragma unroll
    for (int r = 0; r < PROJ_ROWS; ++r) {
        const int row = r0 + r;
        gQ [row * Hn + t] = accq[r] + bq;
        gKc[row * Hn + t] = acck[r] + bk + apK[row * Hn + t];
        gVc[row * Hn + t] = accv[r] + bv + apV[row * Hn + t];
    }
}

// ---------------------------------------------------------------------------
// Attention: one CTA per (b, l), zigzag cost ordering for per-SM balance.
// 256 threads = 4 key-rows in flight x 64 float4 lanes; unroll 4.
// ---------------------------------------------------------------------------
__global__ __launch_bounds__(256)
void attn_kernel(const float4* __restrict__ tK, const float4* __restrict__ tV,
                 const float4* __restrict__ dK, const float4* __restrict__ dV,
                 const unsigned char* __restrict__ time_mask,
                 float4* __restrict__ out)
{
    const int bx   = blockIdx.x;
    const int b    = bx & 3;
    const int rank = bx >> 2;                       // 0..199
    const int l    = (rank & 1) ? (rank >> 1) : (Ln - 1 - (rank >> 1));

    const int t    = threadIdx.x;
    const int msub = t >> 6;
    const int qd   = t & 63;
    const int head = qd >> 4;

    __shared__ float  sW[NHn][Ln];
    __shared__ float4 sRed[4][64];
    __shared__ float  qsh[Hn];

    const float4* __restrict__ Kc4 = g_Kc4;
    const float4* __restrict__ Vc4 = g_Vc4;
    const float*  __restrict__ gQ  = (const float*)g_Q4;

    qsh[t] = gQ[(size_t)(b * Ln + l) * Hn + t];
    __syncthreads();
    const float4 qv = *reinterpret_cast<const float4*>(&qsh[qd * 4]);

    const bool tm   = time_mask[b * Ln + l] != 0;
    const int  mEnd = tm ? Ln : (l + 1);
    const size_t rowBase = ((size_t)(b * Ln + l)) * Ln;

    if (!tm) {
        // ---- pass 1: logits ----
        #pragma unroll 4
        for (int m0 = 0; m0 < mEnd; m0 += 4) {
            const int m = m0 + msub;
            float s = 0.f;
            if (m < mEnd) {
                const size_t off = (rowBase + (size_t)m) * 64 + qd;
                const float4 a = tK[off];
                const float4 c = dK[off];
                const float4 k = Kc4[(size_t)(b * Ln + m) * 64 + qd];
                s = qv.x * (a.x + c.x + k.x) + qv.y * (a.y + c.y + k.y)
                  + qv.z * (a.z + c.z + k.z) + qv.w * (a.w + c.w + k.w);
            }
            s += __shfl_xor_sync(0xffffffffu, s, 8);
            s += __shfl_xor_sync(0xffffffffu, s, 4);
            s += __shfl_xor_sync(0xffffffffu, s, 2);
            s += __shfl_xor_sync(0xffffffffu, s, 1);
            if (m < mEnd && (qd & 15) == 0)
                sW[head][m] = s;
        }
        __syncthreads();

        // ---- pass 2: softmax, one warp per head ----
        if (t < 128) {
            const int h    = t >> 5;
            const int lane = t & 31;
            float mx = -3.4e38f;
            for (int m = lane; m < mEnd; m += 32) mx = fmaxf(mx, sW[h][m]);
            #pragma unroll
            for (int o = 16; o; o >>= 1) mx = fmaxf(mx, __shfl_xor_sync(0xffffffffu, mx, o));
            float sum = 0.f;
            for (int m = lane; m < mEnd; m += 32) {
                const float e = __expf(0.125f * (sW[h][m] - mx));
                sW[h][m] = e;
                sum += e;
            }
            #pragma unroll
            for (int o = 16; o; o >>= 1) sum += __shfl_xor_sync(0xffffffffu, sum, o);
            const float inv = 1.f / sum;
            for (int m = lane; m < mEnd; m += 32) sW[h][m] *= inv;
        }
    } else {
        const float u = 1.f / (float)Ln;
        for (int m = t; m < Ln; m += 256) {
            sW[0][m] = u; sW[1][m] = u; sW[2][m] = u; sW[3][m] = u;
        }
    }
    __syncthreads();

    // ---- pass 3: weighted value sum ----
    float4 acc = make_float4(0.f, 0.f, 0.f, 0.f);
    #pragma unroll 4
    for (int m0 = 0; m0 < mEnd; m0 += 4) {
        const int m = m0 + msub;
        if (m < mEnd) {
            const float  a   = sW[head][m];
            const size_t off = (rowBase + (size_t)m) * 64 + qd;
            const float4 x = tV[off];
            const float4 y = dV[off];
            const float4 v = Vc4[(size_t)(b * Ln + m) * 64 + qd];
            acc.x += a * (x.x + y.x + v.x);
            acc.y += a * (x.y + y.y + v.y);
            acc.z += a * (x.z + y.z + v.z);
            acc.w += a * (x.w + y.w + v.w);
        }
    }
    sRed[msub][qd] = acc;
    __syncthreads();
    if (msub == 0) {
        float4 o = sRed[0][qd];
        #pragma unroll
        for (int r = 1; r < 4; ++r) {
            const float4 rv = sRed[r][qd];
            o.x += rv.x; o.y += rv.y; o.z += rv.z; o.w += rv.w;
        }
        out[(size_t)(b * Ln + l) * 64 + qd] = o;
    }
}

// ---------------------------------------------------------------------------
extern "C" void kernel_launch(void* const* d_in, const int* in_sizes, int n_in,
                              void* d_out, int out_size)
{
    const float4* queries = (const float4*)d_in[0];
    const float4* keys    = (const float4*)d_in[1];
    const float4* tK      = (const float4*)d_in[2];
    const float4* tV      = (const float4*)d_in[3];
    const float4* dK      = (const float4*)d_in[4];
    const float4* dV      = (const float4*)d_in[5];
    const float* apK      = (const float*)d_in[6];
    const float* apV      = (const float*)d_in[7];
    const float4* Qw      = (const float4*)d_in[8];
    const float* Qb       = (const float*)d_in[9];
    const float4* Kw      = (const float4*)d_in[10];
    const float* Kb       = (const float*)d_in[11];
    const float4* Vw      = (const float4*)d_in[12];
    const float* Vb       = (const float*)d_in[13];
    const unsigned char* time_mask = (const unsigned char*)d_in[14];

    proj_kernel<<<(Bn * Ln) / PROJ_ROWS, 256>>>(queries, keys, apK, apV,
                                                Qw, Qb, Kw, Kb, Vw, Vb);
    attn_kernel<<<Bn * Ln, 256>>>(tK, tV, dK, dV, time_mask, (float4*)d_out);
}

// round 5
// speedup vs baseline: 1.8447x; 1.8447x over previous
#include <cuda_runtime.h>

#define Bn 4
#define Ln 200
#define Hn 256
#define NHn 4
#define HSn 64
#define Mrows (Bn * Ln)        // 800

__device__ float4 g_Q4 [Bn * Ln * (Hn / 4)];
__device__ float4 g_Kc4[Bn * Ln * (Hn / 4)];
__device__ float4 g_Vc4[Bn * Ln * (Hn / 4)];

// ---------------------------------------------------------------------------
// Tiled SGEMM projection. Grid (13, 4, 3): 64-row x 64-col tiles, z selects
// {Q from queries, Kc from keys, Vc from keys}. 256 thr = 16x16, each 4x4
// outputs. Inner step: 2x LDS.128 + 16 FMA. Epilogue fuses bias (+abs_pos).
// ---------------------------------------------------------------------------
__global__ __launch_bounds__(256)
void proj_sgemm(const float4* __restrict__ queries,
                const float4* __restrict__ keys,
                const float4* __restrict__ apK4,
                const float4* __restrict__ apV4,
                const float4* __restrict__ Qw4, const float* __restrict__ Qb,
                const float4* __restrict__ Kw4, const float* __restrict__ Kb,
                const float4* __restrict__ Vw4, const float* __restrict__ Vb)
{
    __shared__ alignas(16) float xs[16][68];   // xs[kk][row]  (68: pad, 16B-aligned rows)
    __shared__ alignas(16) float ws[16][68];   // ws[kk][col]

    const int z   = blockIdx.z;                // 0=Q, 1=Kc, 2=Vc
    const int rm0 = blockIdx.x * 64;           // row tile base (may overrun 800)
    const int cn0 = blockIdx.y * 64;           // col tile base

    const float4* __restrict__ X = (z == 0) ? queries : keys;
    const float4* __restrict__ W = (z == 0) ? Qw4 : (z == 1) ? Kw4 : Vw4;
    const float*  __restrict__ Bv = (z == 0) ? Qb : (z == 1) ? Kb : Vb;

    const int t    = threadIdx.x;
    const int tx   = t & 15;
    const int ty   = t >> 4;
    const int lrow = t >> 2;                   // 0..63 (staging)
    const int lq   = t & 3;                    // which float4 in 16-wide k chunk

    float acc[4][4];
    #pragma unroll
    for (int i = 0; i < 4; ++i)
        #pragma unroll
        for (int j = 0; j < 4; ++j) acc[i][j] = 0.f;

    const int xr = min(rm0 + lrow, Mrows - 1); // clamp; out-of-range rows discarded
    const int wc = cn0 + lrow;

    for (int k0 = 0; k0 < Hn; k0 += 16) {
        const float4 xv = X[xr * (Hn / 4) + (k0 >> 2) + lq];
        const float4 wv = W[wc * (Hn / 4) + (k0 >> 2) + lq];
        __syncthreads();
        xs[lq * 4 + 0][lrow] = xv.x; xs[lq * 4 + 1][lrow] = xv.y;
        xs[lq * 4 + 2][lrow] = xv.z; xs[lq * 4 + 3][lrow] = xv.w;
        ws[lq * 4 + 0][lrow] = wv.x; ws[lq * 4 + 1][lrow] = wv.y;
        ws[lq * 4 + 2][lrow] = wv.z; ws[lq * 4 + 3][lrow] = wv.w;
        __syncthreads();
        #pragma unroll
        for (int kk = 0; kk < 16; ++kk) {
            const float4 a = *reinterpret_cast<const float4*>(&xs[kk][ty * 4]);
            const float4 w = *reinterpret_cast<const float4*>(&ws[kk][tx * 4]);
            acc[0][0] += a.x * w.x; acc[0][1] += a.x * w.y; acc[0][2] += a.x * w.z; acc[0][3] += a.x * w.w;
            acc[1][0] += a.y * w.x; acc[1][1] += a.y * w.y; acc[1][2] += a.y * w.z; acc[1][3] += a.y * w.w;
            acc[2][0] += a.z * w.x; acc[2][1] += a.z * w.y; acc[2][2] += a.z * w.z; acc[2][3] += a.z * w.w;
            acc[3][0] += a.w * w.x; acc[3][1] += a.w * w.y; acc[3][2] += a.w * w.z; acc[3][3] += a.w * w.w;
        }
    }

    // epilogue: bias (+abs_pos for K/V), vectorized stores
    const int colBase = cn0 + tx * 4;
    const float4 bias = *reinterpret_cast<const float4*>(&Bv[colBase]);
    float4* __restrict__ dst = (z == 0) ? g_Q4 : (z == 1) ? g_Kc4 : g_Vc4;
    const float4* __restrict__ ap = (z == 1) ? apK4 : apV4;

    #pragma unroll
    for (int i = 0; i < 4; ++i) {
        const int row = rm0 + ty * 4 + i;
        if (row < Mrows) {
            float4 o;
            o.x = acc[i][0] + bias.x; o.y = acc[i][1] + bias.y;
            o.z = acc[i][2] + bias.z; o.w = acc[i][3] + bias.w;
            if (z != 0) {
                const float4 p = ap[row * (Hn / 4) + (colBase >> 2)];
                o.x += p.x; o.y += p.y; o.z += p.z; o.w += p.w;
            }
            dst[row * (Hn / 4) + (colBase >> 2)] = o;
        }
    }
}

// ---------------------------------------------------------------------------
// Attention (R2 config — best measured: 58.8us, DRAM 72%).
// One CTA per (b, row-pair): pairing l and L-1-l makes per-CTA causal work
// exactly L+1 -> balanced. 512 threads = 8 key-rows in flight x 64 lanes.
// ---------------------------------------------------------------------------
__global__ __launch_bounds__(512)
void attn_kernel(const float4* __restrict__ tK, const float4* __restrict__ tV,
                 const float4* __restrict__ dK, const float4* __restrict__ dV,
                 const unsigned char* __restrict__ time_mask,
                 float4* __restrict__ out)
{
    const int bx = blockIdx.x;               // 0..399
    const int b  = bx & (Bn - 1);
    const int p  = bx >> 2;                  // 0..99
    const int t    = threadIdx.x;
    const int msub = t >> 6;                 // 0..7
    const int qd   = t & 63;
    const int head = qd >> 4;

    __shared__ float  sW[NHn][Ln];
    __shared__ float4 sRed[8][64];
    __shared__ float  qsh[Hn];

    const float4* __restrict__ Kc4 = g_Kc4;
    const float4* __restrict__ Vc4 = g_Vc4;
    const float*  __restrict__ gQ  = (const float*)g_Q4;

    #pragma unroll 1
    for (int rr = 0; rr < 2; ++rr) {
        const int l = rr ? p : (Ln - 1 - p);   // heavy row first

        if (t < Hn) qsh[t] = gQ[(size_t)(b * Ln + l) * Hn + t];
        __syncthreads();
        const float4 qv = *reinterpret_cast<const float4*>(&qsh[qd * 4]);

        const bool tm   = time_mask[b * Ln + l] != 0;
        const int  mEnd = tm ? Ln : (l + 1);
        const size_t rowBase = ((size_t)(b * Ln + l)) * Ln;

        if (!tm) {
            #pragma unroll 2
            for (int m0 = 0; m0 < mEnd; m0 += 8) {
                const int m = m0 + msub;
                float s = 0.f;
                if (m < mEnd) {
                    const size_t off = (rowBase + (size_t)m) * 64 + qd;
                    const float4 a = tK[off];
                    const float4 c = dK[off];
                    const float4 k = Kc4[(size_t)(b * Ln + m) * 64 + qd];
                    s = qv.x * (a.x + c.x + k.x) + qv.y * (a.y + c.y + k.y)
                      + qv.z * (a.z + c.z + k.z) + qv.w * (a.w + c.w + k.w);
                }
                s += __shfl_xor_sync(0xffffffffu, s, 8);
                s += __shfl_xor_sync(0xffffffffu, s, 4);
                s += __shfl_xor_sync(0xffffffffu, s, 2);
                s += __shfl_xor_sync(0xffffffffu, s, 1);
                if (m < mEnd && (qd & 15) == 0)
                    sW[head][m] = s;
            }
            __syncthreads();

            if (t < 128) {
                const int h    = t >> 5;
                const int lane = t & 31;
                float mx = -3.4e38f;
                for (int m = lane; m < mEnd; m += 32) mx = fmaxf(mx, sW[h][m]);
                #pragma unroll
                for (int o = 16; o; o >>= 1) mx = fmaxf(mx, __shfl_xor_sync(0xffffffffu, mx, o));
                float sum = 0.f;
                for (int m = lane; m < mEnd; m += 32) {
                    const float e = __expf(0.125f * (sW[h][m] - mx));  // 1/sqrt(64)
                    sW[h][m] = e;
                    sum += e;
                }
                #pragma unroll
                for (int o = 16; o; o >>= 1) sum += __shfl_xor_sync(0xffffffffu, sum, o);
                const float inv = 1.f / sum;
                for (int m = lane; m < mEnd; m += 32) sW[h][m] *= inv;
            }
        } else {
            const float u = 1.f / (float)Ln;
            for (int m = t; m < Ln; m += 512) {
                sW[0][m] = u; sW[1][m] = u; sW[2][m] = u; sW[3][m] = u;
            }
        }
        __syncthreads();

        float4 acc = make_float4(0.f, 0.f, 0.f, 0.f);
        #pragma unroll 2
        for (int m0 = 0; m0 < mEnd; m0 += 8) {
            const int m = m0 + msub;
            if (m < mEnd) {
                const float  a   = sW[head][m];
                const size_t off = (rowBase + (size_t)m) * 64 + qd;
                const float4 x = tV[off];
                const float4 y = dV[off];
                const float4 v = Vc4[(size_t)(b * Ln + m) * 64 + qd];
                acc.x += a * (x.x + y.x + v.x);
                acc.y += a * (x.y + y.y + v.y);
                acc.z += a * (x.z + y.z + v.z);
                acc.w += a * (x.w + y.w + v.w);
            }
        }
        sRed[msub][qd] = acc;
        __syncthreads();
        if (msub == 0) {
            float4 o = sRed[0][qd];
            #pragma unroll
            for (int r = 1; r < 8; ++r) {
                const float4 rv = sRed[r][qd];
                o.x += rv.x; o.y += rv.y; o.z += rv.z; o.w += rv.w;
            }
            out[(size_t)(b * Ln + l) * 64 + qd] = o;
        }
        __syncthreads();
    }
}

// ---------------------------------------------------------------------------
extern "C" void kernel_launch(void* const* d_in, const int* in_sizes, int n_in,
                              void* d_out, int out_size)
{
    const float4* queries = (const float4*)d_in[0];
    const float4* keys    = (const float4*)d_in[1];
    const float4* tK      = (const float4*)d_in[2];
    const float4* tV      = (const float4*)d_in[3];
    const float4* dK      = (const float4*)d_in[4];
    const float4* dV      = (const float4*)d_in[5];
    const float4* apK     = (const float4*)d_in[6];
    const float4* apV     = (const float4*)d_in[7];
    const float4* Qw      = (const float4*)d_in[8];
    const float* Qb       = (const float*)d_in[9];
    const float4* Kw      = (const float4*)d_in[10];
    const float* Kb       = (const float*)d_in[11];
    const float4* Vw      = (const float4*)d_in[12];
    const float* Vb       = (const float*)d_in[13];
    const unsigned char* time_mask = (const unsigned char*)d_in[14];

    proj_sgemm<<<dim3(13, 4, 3), 256>>>(queries, keys, apK, apV,
                                        Qw, Qb, Kw, Kb, Vw, Vb);
    attn_kernel<<<(Bn * Ln) / 2, 512>>>(tK, tV, dK, dV, time_mask, (float4*)d_out);
}